// round 7
// baseline (speedup 1.0000x reference)
#include <cuda_runtime.h>
#include <cstdint>

#define BATCH 8
#define NPTS  2048
#define CIN   64
#define NE    192            // e rows (3*64)
#define NIP   256            // H width: [c(64) | e(192)]
#define MT    128            // a-rows per CTA
#define KC    128            // b's per chunk
#define KP    256            // k' (int8 digit pairs) per chunk
#define NCHUNK (NPTS / KC)   // 16
#define THREADS 256
#define QMAX  8128.0f

// Static device scratch (allocation is forbidden)
__device__ float g_E[(size_t)BATCH * NE * NPTS];          // [z][i''][b]
__device__ float g_Hf[(size_t)BATCH * NIP * NPTS];        // [z][i'][b] f32
__device__ float g_rmax[BATCH * NIP];                     // per-row |v| max
__device__ __align__(128) char g_Hq[(size_t)BATCH * NIP * NPTS * 2]; // [z][i'][k'=2b+{hi,lo}]

// ---------------- smem layout (byte offsets) ----------------
#define AROW     272u
#define A_OFF    0u
#define A_BYTES  (128u * AROW)          // 34816 (single stage)
#define B_OFF    34816u
#define B_STAGE  (256u * AROW)          // 69632, 2 stages -> 174080
#define GBP_OFF  174080u                // packed gb, 2 x 1536
#define GBQ_OFF  177152u                // float4 gb slots, 136*16 = 2176
#define GA_OFF   179328u                // 128 x float4
#define SC_OFF   181376u                // 256 f32 dequant scales
#define SMEM_BYTES (SC_OFF + 1024u)     // 182400

__device__ __forceinline__ uint32_t smem_u32(const void* p) {
    uint32_t a;
    asm("{ .reg .u64 t; cvta.to.shared.u64 t, %1; cvt.u32.u64 %0, t; }" : "=r"(a) : "l"(p));
    return a;
}
__device__ __forceinline__ void cpasync16(uint32_t dst, const void* src) {
    asm volatile("cp.async.cg.shared.global [%0], [%1], 16;" :: "r"(dst), "l"(src) : "memory");
}
__device__ __forceinline__ void ldsm_x4(uint32_t& r0, uint32_t& r1, uint32_t& r2, uint32_t& r3,
                                        uint32_t addr) {
    asm volatile("ldmatrix.sync.aligned.m8n8.x4.shared.b16 {%0,%1,%2,%3}, [%4];"
                 : "=r"(r0), "=r"(r1), "=r"(r2), "=r"(r3) : "r"(addr));
}
__device__ __forceinline__ void imma16832(int& d0, int& d1, int& d2, int& d3,
                                          uint32_t a0, uint32_t a1, uint32_t a2, uint32_t a3,
                                          uint32_t b0, uint32_t b1) {
    asm volatile(
        "mma.sync.aligned.m16n8k32.row.col.s32.s8.s8.s32 "
        "{%0,%1,%2,%3}, {%4,%5,%6,%7}, {%8,%9}, {%0,%1,%2,%3};"
        : "+r"(d0), "+r"(d1), "+r"(d2), "+r"(d3)
        : "r"(a0), "r"(a1), "r"(a2), "r"(a3), "r"(b0), "r"(b1));
}

// ---------------------------------------------------------------------------
// Prep 1: E[z][i''][b] = sum_j feat[z][b][j] * Wk[x][i][j].  Also zeroes rmax
// (stream order guarantees completion before prep_h).
// ---------------------------------------------------------------------------
__global__ __launch_bounds__(256) void prep_e_kernel(const float* __restrict__ feat,
                                                     const float* __restrict__ Wk) {
    __shared__ float s_wk[3 * 64 * 64];
    const int z  = blockIdx.y;
    const int b0 = blockIdx.x * 64;
    const int t  = threadIdx.x;
    if (blockIdx.x == 0 && blockIdx.y == 0)
        for (int m = t; m < BATCH * NIP; m += 256) g_rmax[m] = 0.0f;
    for (int m = t; m < 3 * 64 * 64 / 4; m += 256)
        reinterpret_cast<float4*>(s_wk)[m] = reinterpret_cast<const float4*>(Wk)[m];

    const int bl = t & 63, q = t >> 6;
    const int b = b0 + bl;
    float4 fr[16];
    const float4* fp = reinterpret_cast<const float4*>(feat + ((size_t)z * NPTS + b) * CIN);
#pragma unroll
    for (int c = 0; c < 16; c++) fr[c] = fp[c];
    __syncthreads();

    float* Eb = g_E + (size_t)z * NE * NPTS + b;
#pragma unroll 1
    for (int n = 0; n < 48; n++) {
        const int ii = q * 48 + n;
        const float4* w = reinterpret_cast<const float4*>(s_wk + ii * 64);
        float a0 = 0.f, a1 = 0.f, a2 = 0.f, a3 = 0.f;
#pragma unroll
        for (int c = 0; c < 16; c++) {
            const float4 wv = w[c];
            a0 = fmaf(fr[c].x, wv.x, a0);
            a1 = fmaf(fr[c].y, wv.y, a1);
            a2 = fmaf(fr[c].z, wv.z, a2);
            a3 = fmaf(fr[c].w, wv.w, a3);
        }
        Eb[(size_t)ii * NPTS] = (a0 + a1) + (a2 + a3);
    }
}

// ---------------------------------------------------------------------------
// Prep 2: Hf[z][i'][b] (f32) and per-row max |v| via warp-reduce + atomicMax.
// i'<64: c_b = sum_x g[b,x]*E[64x+i']; else E[i'-64].
// ---------------------------------------------------------------------------
__global__ __launch_bounds__(128) void prep_h_kernel(const float* __restrict__ geom) {
    const int t   = threadIdx.x;
    const int b   = (blockIdx.x * 128 + t) * 2;
    const int z   = blockIdx.y >> 2;
    const int ig0 = (blockIdx.y & 3) * 64;
    const float* gp0 = geom + ((size_t)z * NPTS + b) * 3;
    const float g00 = gp0[0], g01 = gp0[1], g02 = gp0[2];
    const float g10 = gp0[3], g11 = gp0[4], g12 = gp0[5];
    const float* Ez = g_E + (size_t)z * NE * NPTS;
#pragma unroll 1
    for (int n = 0; n < 64; n++) {
        const int ip = ig0 + n;
        float v0, v1;
        if (ip < 64) {
            const float2 e0 = *reinterpret_cast<const float2*>(Ez + (size_t)ip * NPTS + b);
            const float2 e1 = *reinterpret_cast<const float2*>(Ez + (size_t)(64 + ip) * NPTS + b);
            const float2 e2 = *reinterpret_cast<const float2*>(Ez + (size_t)(128 + ip) * NPTS + b);
            v0 = fmaf(g00, e0.x, fmaf(g01, e1.x, g02 * e2.x));
            v1 = fmaf(g10, e0.y, fmaf(g11, e1.y, g12 * e2.y));
        } else {
            const float2 e = *reinterpret_cast<const float2*>(Ez + (size_t)(ip - 64) * NPTS + b);
            v0 = e.x; v1 = e.y;
        }
        *reinterpret_cast<float2*>(g_Hf + ((size_t)(z * NIP + ip)) * NPTS + b) =
            make_float2(v0, v1);
        float am = fmaxf(fabsf(v0), fabsf(v1));
#pragma unroll
        for (int o = 16; o > 0; o >>= 1)
            am = fmaxf(am, __shfl_xor_sync(0xffffffffu, am, o));
        if ((t & 31) == 0)
            atomicMax(reinterpret_cast<int*>(&g_rmax[z * NIP + ip]), __float_as_int(am));
    }
}

// ---------------------------------------------------------------------------
// Prep 3: quantize.  q = rn(v*8128/rmax) = 64*qhi + qlo (qhi,qlo int8, exact).
// Output interleaved digits: Hq[z][i'][2b] = qhi, [2b+1] = qlo.
// ---------------------------------------------------------------------------
__global__ __launch_bounds__(256) void quant_kernel() {
    const int row = blockIdx.y;                 // i'
    const int z   = blockIdx.z;
    const int b0  = blockIdx.x * 1024 + threadIdx.x * 4;
    const float rmax = fmaxf(g_rmax[z * NIP + row], 1e-30f);
    const float inv = QMAX / rmax;
    const float4 v = *reinterpret_cast<const float4*>(
        g_Hf + ((size_t)(z * NIP + row)) * NPTS + b0);
    int q[4];
    q[0] = __float2int_rn(v.x * inv); q[1] = __float2int_rn(v.y * inv);
    q[2] = __float2int_rn(v.z * inv); q[3] = __float2int_rn(v.w * inv);
    uint32_t w0 = 0, w1 = 0;
#pragma unroll
    for (int u = 0; u < 2; u++) {
        const int qh0 = (q[u] + 32) >> 6, ql0 = q[u] - (qh0 << 6);
        const int qh1 = (q[2 + u] + 32) >> 6, ql1 = q[2 + u] - (qh1 << 6);
        w0 |= ((uint32_t)(qh0 & 0xFF) | ((uint32_t)(ql0 & 0xFF) << 8)) << (16 * u);
        w1 |= ((uint32_t)(qh1 & 0xFF) | ((uint32_t)(ql1 & 0xFF) << 8)) << (16 * u);
    }
    *reinterpret_cast<uint2*>(g_Hq + ((size_t)(z * NIP + row)) * NPTS * 2 + 2 * b0) =
        make_uint2(w0, w1);
}

// ---------------------------------------------------------------------------
// Main: per CTA (z, 128 a-rows): P[128 x 256] = A @ Hq via IMMA s8, where
// A k'-pairs = (64*m, m) and B k'-pairs = (qhi, qlo)  ->  P = sum_b m*q exact.
// Epilogue: out[a,i] = sc[i]*P[a,i] - sum_x ga[x]*sc[64+64x+i]*P[a,64+64x+i].
// ---------------------------------------------------------------------------
__global__ __launch_bounds__(THREADS, 1) void conv_imma_kernel(
    const float* __restrict__ geom, float* __restrict__ out)
{
    extern __shared__ __align__(16) char smem[];
    const uint32_t su = smem_u32(smem);

    const int z  = blockIdx.y;
    const int a0 = blockIdx.x * MT;
    const int t  = threadIdx.x;
    const int wid = t >> 5, lane = t & 31;
    const int m0 = (wid >> 2) * 64, n0 = (wid & 3) * 64;

    const float* gz = geom + (size_t)z * NPTS * 3;

    // stage g_a and dequant scales
    if (t < MT) {
        const float* gp = gz + (size_t)(a0 + t) * 3;
        *reinterpret_cast<float4*>(smem + GA_OFF + t * 16) =
            make_float4(gp[0], gp[1], gp[2], 0.0f);
    }
    *reinterpret_cast<float*>(smem + SC_OFF + t * 4) =
        g_rmax[z * NIP + t] * (1.0f / QMAX);

    // prologue: chunk-0 B tile + packed geometry
#pragma unroll
    for (int it = 0; it < 16; it++) {
        const int m = t + THREADS * it;
        const int row = m >> 4, c16 = m & 15;
        cpasync16(su + B_OFF + row * AROW + c16 * 16,
                  g_Hq + ((size_t)(z * NIP + row)) * NPTS * 2 + c16 * 16);
    }
    if (t < 96) cpasync16(su + GBP_OFF + t * 16, (const char*)gz + t * 16);
    asm volatile("cp.async.commit_group;" ::: "memory");
    __syncthreads();

    // ldmatrix per-lane bases (row stride 272 = odd*16 -> conflict-free)
    const uint32_t aLane = (uint32_t)((m0 + ((lane >> 3) & 1) * 8 + (lane & 7)) * AROW
                                      + (lane >> 4) * 16);
    const uint32_t bLane = (uint32_t)((n0 + ((lane >> 4) & 1) * 8 + (lane & 7)) * AROW
                                      + ((lane >> 3) & 1) * 16);
    const int rg = t >> 1, hg = t & 1;   // maskgen: row, k-half
    const float4 gaR = *reinterpret_cast<const float4*>(smem + GA_OFF + rg * 16);

    int d[4][8][4];
#pragma unroll
    for (int mt = 0; mt < 4; mt++)
#pragma unroll
        for (int nt = 0; nt < 8; nt++)
#pragma unroll
            for (int r = 0; r < 4; r++) d[mt][nt][r] = 0;

#pragma unroll 1
    for (int i = 0; i < NCHUNK; i++) {
        const uint32_t p = (uint32_t)(i & 1);

        __syncthreads();   // prior-stage reads complete

        if (i + 1 < NCHUNK) {
            const int b1 = (i + 1) * KC;
            const uint32_t bst = su + B_OFF + (p ^ 1u) * B_STAGE;
#pragma unroll
            for (int it = 0; it < 16; it++) {
                const int m = t + THREADS * it;
                const int row = m >> 4, c16 = m & 15;
                cpasync16(bst + row * AROW + c16 * 16,
                          g_Hq + ((size_t)(z * NIP + row)) * NPTS * 2 + 2 * b1 + c16 * 16);
            }
            if (t < 96)
                cpasync16(su + GBP_OFF + (p ^ 1u) * 1536 + t * 16,
                          (const char*)(gz + (size_t)b1 * 3) + t * 16);
            asm volatile("cp.async.commit_group;" ::: "memory");
            asm volatile("cp.async.wait_group 1;" ::: "memory");
        } else {
            asm volatile("cp.async.wait_group 0;" ::: "memory");
        }

        // gb packed -> float4 slots (k + k/16)
        if (t < KC) {
            const float* gp = reinterpret_cast<const float*>(smem + GBP_OFF + p * 1536) + t * 3;
            const int slot = t + (t >> 4);
            *reinterpret_cast<float4*>(smem + GBQ_OFF + slot * 16) =
                make_float4(gp[0], gp[1], gp[2], 0.0f);
        }
        __syncthreads();

        // mask tile A[128][256 k'] int8: byte pair (64*m, m) per b
        {
            char* arow = smem + A_OFF + rg * AROW + hg * 128;
            const char* gbq = smem + GBQ_OFF;
#pragma unroll
            for (int u = 0; u < 32; u++) {
                const int k0 = hg * 64 + 2 * u;
                const float4 q0 = *reinterpret_cast<const float4*>(gbq + (k0 + (k0 >> 4)) * 16);
                const int k1 = k0 + 1;
                const float4 q1 = *reinterpret_cast<const float4*>(gbq + (k1 + (k1 >> 4)) * 16);
                const float dx0 = q0.x - gaR.x, dy0 = q0.y - gaR.y, dz0 = q0.z - gaR.z;
                const float dx1 = q1.x - gaR.x, dy1 = q1.y - gaR.y, dz1 = q1.z - gaR.z;
                const float nn0 = fmaf(dx0, dx0, fmaf(dy0, dy0, dz0 * dz0));
                const float nn1 = fmaf(dx1, dx1, fmaf(dy1, dy1, dz1 * dz1));
                const uint32_t v = (nn0 < 1.0f ? 0x0140u : 0u)
                                 | (nn1 < 1.0f ? 0x01400000u : 0u);
                *reinterpret_cast<uint32_t*>(arow + u * 4) = v;
            }
        }
        __syncthreads();

        // ldmatrix fragments + 256 IMMAs per warp
        {
            const uint32_t Ab = su + A_OFF + aLane;
            const uint32_t Bb = su + B_OFF + p * B_STAGE + bLane;
#pragma unroll
            for (int kk = 0; kk < 8; kk++) {
                uint32_t af[4][4];
#pragma unroll
                for (int mt = 0; mt < 4; mt++)
                    ldsm_x4(af[mt][0], af[mt][1], af[mt][2], af[mt][3],
                            Ab + (uint32_t)(mt * 16 * AROW + kk * 32));
#pragma unroll
                for (int ntp = 0; ntp < 4; ntp++) {
                    uint32_t b0, b1, b2, b3;
                    ldsm_x4(b0, b1, b2, b3,
                            Bb + (uint32_t)(ntp * 16 * AROW + kk * 32));
#pragma unroll
                    for (int mt = 0; mt < 4; mt++) {
                        imma16832(d[mt][2*ntp][0], d[mt][2*ntp][1], d[mt][2*ntp][2], d[mt][2*ntp][3],
                                  af[mt][0], af[mt][1], af[mt][2], af[mt][3], b0, b1);
                        imma16832(d[mt][2*ntp+1][0], d[mt][2*ntp+1][1], d[mt][2*ntp+1][2], d[mt][2*ntp+1][3],
                                  af[mt][0], af[mt][1], af[mt][2], af[mt][3], b2, b3);
                    }
                }
            }
        }
    }

    // ---- epilogue: raw P (exact s32 -> f32) to smem, then scaled combine ----
    __syncthreads();
    float* P = reinterpret_cast<float*>(smem);   // [128][260]
    const int fr = lane >> 2, fc = lane & 3;
#pragma unroll
    for (int mt = 0; mt < 4; mt++) {
#pragma unroll
        for (int nt = 0; nt < 8; nt++) {
            const int R0 = m0 + mt * 16 + fr;
            const int C  = n0 + nt * 8 + 2 * fc;
            *reinterpret_cast<float2*>(P + R0 * 260 + C) =
                make_float2((float)d[mt][nt][0], (float)d[mt][nt][1]);
            *reinterpret_cast<float2*>(P + (R0 + 8) * 260 + C) =
                make_float2((float)d[mt][nt][2], (float)d[mt][nt][3]);
        }
    }
    __syncthreads();

    {
        const int al = t >> 1, iq = t & 1;
        const float4 ga4 = *reinterpret_cast<const float4*>(smem + GA_OFF + al * 16);
        const float* sc = reinterpret_cast<const float*>(smem + SC_OFF);
        float* orow = out + ((size_t)z * NPTS + a0 + al) * 64;
        const float* Pr = P + al * 260;
#pragma unroll
        for (int w = 0; w < 8; w++) {
            const int i0 = iq * 32 + w * 4;
            const float4 vc = *reinterpret_cast<const float4*>(Pr + i0);
            const float4 v1 = *reinterpret_cast<const float4*>(Pr + 64 + i0);
            const float4 v2 = *reinterpret_cast<const float4*>(Pr + 128 + i0);
            const float4 v3 = *reinterpret_cast<const float4*>(Pr + 192 + i0);
            const float4 sc0 = *reinterpret_cast<const float4*>(sc + i0);
            const float4 sc1 = *reinterpret_cast<const float4*>(sc + 64 + i0);
            const float4 sc2 = *reinterpret_cast<const float4*>(sc + 128 + i0);
            const float4 sc3 = *reinterpret_cast<const float4*>(sc + 192 + i0);
            float4 o;
            o.x = vc.x * sc0.x - ga4.x * (v1.x * sc1.x) - ga4.y * (v2.x * sc2.x) - ga4.z * (v3.x * sc3.x);
            o.y = vc.y * sc0.y - ga4.x * (v1.y * sc1.y) - ga4.y * (v2.y * sc2.y) - ga4.z * (v3.y * sc3.y);
            o.z = vc.z * sc0.z - ga4.x * (v1.z * sc1.z) - ga4.y * (v2.z * sc2.z) - ga4.z * (v3.z * sc3.z);
            o.w = vc.w * sc0.w - ga4.x * (v1.w * sc1.w) - ga4.y * (v2.w * sc2.w) - ga4.z * (v3.w * sc3.w);
            *reinterpret_cast<float4*>(orow + i0) = o;
        }
    }
}

// ---------------------------------------------------------------------------
// Launcher. Inputs: features [8,2048,64] f32, geometry [8,2048,3] f32,
// Wk [3,64,64] f32. Output [8,2048,64] f32.
// ---------------------------------------------------------------------------
extern "C" void kernel_launch(void* const* d_in, const int* in_sizes, int n_in,
                              void* d_out, int out_size) {
    const float* feat = (const float*)d_in[0];
    const float* geom = (const float*)d_in[1];
    const float* Wk   = (const float*)d_in[2];
    float* out = (float*)d_out;
    (void)in_sizes; (void)n_in; (void)out_size;

    cudaFuncSetAttribute(conv_imma_kernel,
                         cudaFuncAttributeMaxDynamicSharedMemorySize, SMEM_BYTES);

    prep_e_kernel<<<dim3(NPTS / 64, BATCH), 256>>>(feat, Wk);
    prep_h_kernel<<<dim3(NPTS / 256, BATCH * 4), 128>>>(geom);
    quant_kernel<<<dim3(NPTS / 1024, NIP, BATCH), 256>>>();
    conv_imma_kernel<<<dim3(NPTS / MT, BATCH), THREADS, SMEM_BYTES>>>(geom, out);
}

// round 8
// speedup vs baseline: 2.6577x; 2.6577x over previous
#include <cuda_runtime.h>
#include <cuda_bf16.h>
#include <cstdint>

#define BATCH 8
#define NPTS  2048
#define CIN   64
#define NIP   256            // H width: [c(64) | e(192)]
#define MT    128            // a-rows per CTA
#define KC    64             // b's per chunk
#define NCHUNK (NPTS / KC)   // 32
#define THREADS 512

// Static device scratch (allocation is forbidden)
__device__ __align__(128) __nv_bfloat16 g_H[(size_t)2 * BATCH * NIP * NPTS]; // [split][z][i'][b]

// ---- main-kernel smem layout (bytes) ----
#define GEOM_OFF 0u                  // 2048 x float4 = 32768
#define A_OFF    32768u              // 2 x 16384 (128 rows x 128B, SW128)
#define A_STG    16384u
#define B_OFF    65536u              // 2 x 65536 (512 rows x 128B: hi 256 + lo 256)
#define B_STG    65536u
#define SMEM_MAIN (B_OFF + 2u * B_STG)   // 196608

// ---- prep-kernel smem (floats) ----
#define PWK_F   0
#define PE_F    12288                // E tile 192 x 72
#define PGB_F   26112                // 64 x float4
#define SMEM_PREP ((26112 + 256) * 4)    // 105472 B

__device__ __forceinline__ uint32_t smem_u32(const void* p) {
    uint32_t a;
    asm("{ .reg .u64 t; cvta.to.shared.u64 t, %1; cvt.u32.u64 %0, t; }" : "=r"(a) : "l"(p));
    return a;
}
__device__ __forceinline__ void cpasync16(uint32_t dst, const void* src) {
    asm volatile("cp.async.cg.shared.global [%0], [%1], 16;" :: "r"(dst), "l"(src) : "memory");
}
__device__ __forceinline__ void sts32(uint32_t a, uint32_t v) {
    asm volatile("st.shared.b32 [%0], %1;" :: "r"(a), "r"(v) : "memory");
}
__device__ __forceinline__ void ldsm_x4(uint32_t& r0, uint32_t& r1, uint32_t& r2, uint32_t& r3,
                                        uint32_t addr) {
    asm volatile("ldmatrix.sync.aligned.m8n8.x4.shared.b16 {%0,%1,%2,%3}, [%4];"
                 : "=r"(r0), "=r"(r1), "=r"(r2), "=r"(r3) : "r"(addr));
}
__device__ __forceinline__ void mma16816(float& d0, float& d1, float& d2, float& d3,
                                         uint32_t a0, uint32_t a1, uint32_t a2, uint32_t a3,
                                         uint32_t b0, uint32_t b1) {
    asm volatile(
        "mma.sync.aligned.m16n8k16.row.col.f32.bf16.bf16.f32 "
        "{%0,%1,%2,%3}, {%4,%5,%6,%7}, {%8,%9}, {%0,%1,%2,%3};"
        : "+f"(d0), "+f"(d1), "+f"(d2), "+f"(d3)
        : "r"(a0), "r"(a1), "r"(a2), "r"(a3), "r"(b0), "r"(b1));
}

// ---------------------------------------------------------------------------
// Fused prep: per block (z, b-tile of 64):
//   E[192][64] in smem (E[i''=64x+i][b] = sum_j f[b][j] Wk[x][i][j]),
//   then H rows: H[r<64] = c_b = sum_x g[b,x] E[64x+r][b];  H[64+ii] = E[ii].
//   hi/lo bf16 split written straight to g_H [split][z][i'][b].
// ---------------------------------------------------------------------------
__global__ __launch_bounds__(256) void prep_kernel(const float* __restrict__ feat,
                                                   const float* __restrict__ geom,
                                                   const float* __restrict__ Wk) {
    extern __shared__ float sp[];
    float* s_wk = sp + PWK_F;
    float* s_E  = sp + PE_F;
    float4* s_gb = reinterpret_cast<float4*>(sp + PGB_F);

    const int z  = blockIdx.y;
    const int b0 = blockIdx.x * 64;
    const int t  = threadIdx.x;

    for (int m = t; m < 3 * 64 * 64 / 4; m += 256)
        reinterpret_cast<float4*>(s_wk)[m] = reinterpret_cast<const float4*>(Wk)[m];
    if (t < 64) {
        const float* gp = geom + ((size_t)z * NPTS + b0 + t) * 3;
        s_gb[t] = make_float4(gp[0], gp[1], gp[2], 0.0f);
    }

    const int bl = t & 63, q = t >> 6;
    float4 fr[16];
    const float4* fp = reinterpret_cast<const float4*>(
        feat + ((size_t)z * NPTS + b0 + bl) * CIN);
#pragma unroll
    for (int c = 0; c < 16; c++) fr[c] = fp[c];
    __syncthreads();

#pragma unroll 1
    for (int n = 0; n < 48; n++) {
        const int ii = q * 48 + n;
        const float4* w = reinterpret_cast<const float4*>(s_wk + ii * 64);
        float a0 = 0.f, a1 = 0.f, a2 = 0.f, a3 = 0.f;
#pragma unroll
        for (int c = 0; c < 16; c++) {
            const float4 wv = w[c];
            a0 = fmaf(fr[c].x, wv.x, a0);
            a1 = fmaf(fr[c].y, wv.y, a1);
            a2 = fmaf(fr[c].z, wv.z, a2);
            a3 = fmaf(fr[c].w, wv.w, a3);
        }
        s_E[ii * 72 + bl] = (a0 + a1) + (a2 + a3);
    }
    __syncthreads();

    // phase 2: warp w -> rows w*32..w*32+31; lane l -> b pair (2l, 2l+1)
    const int wrp = t >> 5, l = t & 31;
    const float4 gbA = s_gb[2 * l];
    const float4 gbB = s_gb[2 * l + 1];
    uint32_t* Hh = reinterpret_cast<uint32_t*>(g_H);
    uint32_t* Hl = Hh + ((size_t)BATCH * NIP * NPTS) / 2;

#pragma unroll 1
    for (int rr = 0; rr < 32; rr++) {
        const int r = wrp * 32 + rr;
        float v0, v1;
        if (r < 64) {
            const float2 e0 = *reinterpret_cast<const float2*>(&s_E[r * 72 + 2 * l]);
            const float2 e1 = *reinterpret_cast<const float2*>(&s_E[(64 + r) * 72 + 2 * l]);
            const float2 e2 = *reinterpret_cast<const float2*>(&s_E[(128 + r) * 72 + 2 * l]);
            v0 = fmaf(gbA.x, e0.x, fmaf(gbA.y, e1.x, gbA.z * e2.x));
            v1 = fmaf(gbB.x, e0.y, fmaf(gbB.y, e1.y, gbB.z * e2.y));
        } else {
            const float2 e = *reinterpret_cast<const float2*>(&s_E[(r - 64) * 72 + 2 * l]);
            v0 = e.x; v1 = e.y;
        }
        const __nv_bfloat16 h0 = __float2bfloat16(v0);
        const __nv_bfloat16 h1 = __float2bfloat16(v1);
        const __nv_bfloat16 l0 = __float2bfloat16(v0 - __bfloat162float(h0));
        const __nv_bfloat16 l1 = __float2bfloat16(v1 - __bfloat162float(h1));
        const size_t idx = (((size_t)z * NIP + r) * NPTS + b0) / 2 + l;
        Hh[idx] = (uint32_t)__bfloat16_as_ushort(h0) | ((uint32_t)__bfloat16_as_ushort(h1) << 16);
        Hl[idx] = (uint32_t)__bfloat16_as_ushort(l0) | ((uint32_t)__bfloat16_as_ushort(l1) << 16);
    }
}

// issue one chunk's B copies (hi+lo, 512 rows x 128B, SW128-swizzled)
__device__ __forceinline__ void issue_b_copies(uint32_t bst, int z, int b0, int t) {
#pragma unroll
    for (int it = 0; it < 8; it++) {
        const int m = t + THREADS * it;
        const int s = m >> 11, rem = m & 2047, row = rem >> 3, c16 = rem & 7;
        const uint32_t dst = bst + (uint32_t)s * 32768u + (uint32_t)row * 128u
                           + (uint32_t)((c16 ^ (row & 7)) << 4);
        const __nv_bfloat16* src =
            g_H + (((size_t)(s * BATCH + z) * NIP + row) * NPTS + b0 + c16 * 8);
        cpasync16(dst, src);
    }
}

// ---------------------------------------------------------------------------
// Main: per CTA (z, 128 a-rows): P[128 x 256] = M @ (H_hi + H_lo), bf16 HMMA.
// 16 warps, warp tile 32x64, 1 syncthreads per chunk, double-buffered B,
// mask tile A generated in-CTA from smem geometry.
// ---------------------------------------------------------------------------
__global__ __launch_bounds__(THREADS, 1) void conv_mma_kernel(
    const float* __restrict__ geom, float* __restrict__ out)
{
    extern __shared__ __align__(16) char smem[];
    const uint32_t su = smem_u32(smem);
    float4* g4 = reinterpret_cast<float4*>(smem);

    const int z  = blockIdx.y;
    const int a0 = blockIdx.x * MT;
    const int t  = threadIdx.x;
    const int wid = t >> 5, lane = t & 31;
    const int m0 = (wid >> 2) * 32, n0 = (wid & 3) * 64;

    const float* gz = geom + (size_t)z * NPTS * 3;

    // prologue: chunk-0 B copies + stage whole-z geometry as float4
    issue_b_copies(su + B_OFF, z, 0, t);
    asm volatile("cp.async.commit_group;" ::: "memory");
    {
        float* gf = reinterpret_cast<float*>(smem);
        for (int idx = t; idx < NPTS * 3; idx += THREADS)
            gf[(idx / 3) * 4 + (idx % 3)] = gz[idx];
    }
    __syncthreads();

    // maskgen consts: thread t -> row rg, k-quarter sg
    const int rg = t >> 2, sg = t & 3;
    const float4 ga = g4[a0 + rg];
    const uint32_t aw_base = su + A_OFF + (uint32_t)rg * 128u;
    const uint32_t rx = (uint32_t)(rg & 7);

    // ldsm lane bases
    const int rowA = m0 + ((lane >> 3) & 1) * 8 + (lane & 7);
    const uint32_t sA = (uint32_t)(lane >> 4), rxA = (uint32_t)(rowA & 7);
    const int rowB = n0 + ((lane >> 4) & 1) * 8 + (lane & 7);
    const uint32_t sB = (uint32_t)((lane >> 3) & 1), rxB = (uint32_t)(rowB & 7);

    float d[2][8][4];
#pragma unroll
    for (int mt = 0; mt < 2; mt++)
#pragma unroll
        for (int nt = 0; nt < 8; nt++)
#pragma unroll
            for (int r = 0; r < 4; r++) d[mt][nt][r] = 0.0f;

#pragma unroll 1
    for (int i = 0; i < NCHUNK; i++) {
        const uint32_t p = (uint32_t)(i & 1);
        const int b0 = i * KC;

        asm volatile("cp.async.wait_group 0;" ::: "memory");

        // ---- mask tile A[128 x 64] bf16 (SW128), diff-form norm test ----
        {
            const uint32_t ast = aw_base + p * A_STG;
#pragma unroll
            for (int v = 0; v < 8; v++) {
                const int veff = (v + sg) & 7;
                const int k0 = sg * 16 + 2 * veff;
                const float4 q0 = g4[b0 + k0];
                const float4 q1 = g4[b0 + k0 + 1];
                const float dx0 = q0.x - ga.x, dy0 = q0.y - ga.y, dz0 = q0.z - ga.z;
                const float dx1 = q1.x - ga.x, dy1 = q1.y - ga.y, dz1 = q1.z - ga.z;
                const float nn0 = fmaf(dx0, dx0, fmaf(dy0, dy0, dz0 * dz0));
                const float nn1 = fmaf(dx1, dx1, fmaf(dy1, dy1, dz1 * dz1));
                const uint32_t val = (nn0 < 1.0f ? 0x3F80u : 0u)
                                   | (nn1 < 1.0f ? 0x3F800000u : 0u);
                const uint32_t bc = (uint32_t)(2 * k0);
                sts32(ast + (((bc >> 4) ^ rx) << 4) + (bc & 15u), val);
            }
        }
        __syncthreads();   // A(p)+B(p) visible; all warps done with stage p^1

        if (i + 1 < NCHUNK) {
            issue_b_copies(su + B_OFF + (p ^ 1u) * B_STG, z, b0 + KC, t);
            asm volatile("cp.async.commit_group;" ::: "memory");
        }

        // ---- ldmatrix + 128 HMMA per warp ----
        {
            const uint32_t Ast = su + A_OFF + p * A_STG;
            const uint32_t Bst = su + B_OFF + p * B_STG;
#pragma unroll
            for (int kk = 0; kk < 4; kk++) {
                uint32_t af[2][4];
#pragma unroll
                for (int mt = 0; mt < 2; mt++)
                    ldsm_x4(af[mt][0], af[mt][1], af[mt][2], af[mt][3],
                            Ast + (uint32_t)(rowA + mt * 16) * 128u
                                + ((((uint32_t)kk * 2u + sA) ^ rxA) << 4));
#pragma unroll
                for (int s = 0; s < 2; s++) {
                    const uint32_t Bs = Bst + (uint32_t)s * 32768u;
#pragma unroll
                    for (int ntp = 0; ntp < 4; ntp++) {
                        uint32_t b0r, b1r, b2r, b3r;
                        ldsm_x4(b0r, b1r, b2r, b3r,
                                Bs + (uint32_t)(rowB + ntp * 16) * 128u
                                   + ((((uint32_t)kk * 2u + sB) ^ rxB) << 4));
#pragma unroll
                        for (int mt = 0; mt < 2; mt++) {
                            mma16816(d[mt][2*ntp][0], d[mt][2*ntp][1], d[mt][2*ntp][2], d[mt][2*ntp][3],
                                     af[mt][0], af[mt][1], af[mt][2], af[mt][3], b0r, b1r);
                            mma16816(d[mt][2*ntp+1][0], d[mt][2*ntp+1][1], d[mt][2*ntp+1][2], d[mt][2*ntp+1][3],
                                     af[mt][0], af[mt][1], af[mt][2], af[mt][3], b2r, b3r);
                        }
                    }
                }
            }
        }
    }

    // ---- epilogue: P (overlays A/B region), combine, store ----
    __syncthreads();
    float* P = reinterpret_cast<float*>(smem + A_OFF);   // [128][260]
    const int fr = lane >> 2, fc = lane & 3;
#pragma unroll
    for (int mt = 0; mt < 2; mt++) {
#pragma unroll
        for (int nt = 0; nt < 8; nt++) {
            const int R0 = m0 + mt * 16 + fr;
            const int C  = n0 + nt * 8 + 2 * fc;
            *reinterpret_cast<float2*>(P + R0 * 260 + C)       = make_float2(d[mt][nt][0], d[mt][nt][1]);
            *reinterpret_cast<float2*>(P + (R0 + 8) * 260 + C) = make_float2(d[mt][nt][2], d[mt][nt][3]);
        }
    }
    __syncthreads();

    {
        const int al = t >> 2, iq = t & 3;
        const float4 ga4 = g4[a0 + al];
        float* orow = out + ((size_t)z * NPTS + a0 + al) * 64;
        const float* Pr = P + al * 260;
#pragma unroll
        for (int u = 0; u < 4; u++) {
            const int i0 = iq * 16 + u * 4;
            const float4 vc = *reinterpret_cast<const float4*>(Pr + i0);
            const float4 v1 = *reinterpret_cast<const float4*>(Pr + 64 + i0);
            const float4 v2 = *reinterpret_cast<const float4*>(Pr + 128 + i0);
            const float4 v3 = *reinterpret_cast<const float4*>(Pr + 192 + i0);
            float4 o;
            o.x = fmaf(-ga4.z, v3.x, fmaf(-ga4.y, v2.x, fmaf(-ga4.x, v1.x, vc.x)));
            o.y = fmaf(-ga4.z, v3.y, fmaf(-ga4.y, v2.y, fmaf(-ga4.x, v1.y, vc.y)));
            o.z = fmaf(-ga4.z, v3.z, fmaf(-ga4.y, v2.z, fmaf(-ga4.x, v1.z, vc.z)));
            o.w = fmaf(-ga4.z, v3.w, fmaf(-ga4.y, v2.w, fmaf(-ga4.x, v1.w, vc.w)));
            *reinterpret_cast<float4*>(orow + i0) = o;
        }
    }
}

// ---------------------------------------------------------------------------
// Launcher. Inputs: features [8,2048,64] f32, geometry [8,2048,3] f32,
// Wk [3,64,64] f32. Output [8,2048,64] f32.
// ---------------------------------------------------------------------------
extern "C" void kernel_launch(void* const* d_in, const int* in_sizes, int n_in,
                              void* d_out, int out_size) {
    const float* feat = (const float*)d_in[0];
    const float* geom = (const float*)d_in[1];
    const float* Wk   = (const float*)d_in[2];
    float* out = (float*)d_out;
    (void)in_sizes; (void)n_in; (void)out_size;

    cudaFuncSetAttribute(prep_kernel,
                         cudaFuncAttributeMaxDynamicSharedMemorySize, SMEM_PREP);
    cudaFuncSetAttribute(conv_mma_kernel,
                         cudaFuncAttributeMaxDynamicSharedMemorySize, SMEM_MAIN);

    prep_kernel<<<dim3(NPTS / 64, BATCH), 256, SMEM_PREP>>>(feat, geom, Wk);
    conv_mma_kernel<<<dim3(NPTS / MT, BATCH), THREADS, SMEM_MAIN>>>(geom, out);
}

// round 9
// speedup vs baseline: 3.8401x; 1.4449x over previous
#include <cuda_runtime.h>
#include <cuda_fp16.h>
#include <cstdint>

#define BATCH 8
#define NPTS  2048
#define CIN   64
#define NIP   256            // H width: [c(64) | e(192)]
#define MT    64             // a-rows per CTA
#define KC    64             // b's per chunk
#define NCHUNK (NPTS / KC)   // 32
#define THREADS 256

// Static device scratch (allocation is forbidden)
__device__ __align__(128) __half g_H[(size_t)BATCH * NIP * NPTS];  // [z][i'][b] fp16

// ---- main-kernel smem layout (bytes) ----
#define GEOM_OFF 0u                  // 2048 x float4 = 32768
#define A_OFF    32768u              // 2 x 8192 (64 rows x 128B, SW128)
#define A_STG    8192u
#define B_OFF    49152u              // 2 x 32768 (256 rows x 128B, SW128)
#define B_STG    32768u
#define SMEM_MAIN (B_OFF + 2u * B_STG)   // 114688 -> 2 CTAs/SM

// ---- prep-kernel smem (floats) ----
#define PWK_F   0
#define PE_F    12288                // E tile 192 x 72
#define PGB_F   26112                // 64 x float4
#define SMEM_PREP ((26112 + 256) * 4)

__device__ __forceinline__ uint32_t smem_u32(const void* p) {
    uint32_t a;
    asm("{ .reg .u64 t; cvta.to.shared.u64 t, %1; cvt.u32.u64 %0, t; }" : "=r"(a) : "l"(p));
    return a;
}
__device__ __forceinline__ void cpasync16(uint32_t dst, const void* src) {
    asm volatile("cp.async.cg.shared.global [%0], [%1], 16;" :: "r"(dst), "l"(src) : "memory");
}
__device__ __forceinline__ void sts32(uint32_t a, uint32_t v) {
    asm volatile("st.shared.b32 [%0], %1;" :: "r"(a), "r"(v) : "memory");
}
__device__ __forceinline__ void ldsm_x4(uint32_t& r0, uint32_t& r1, uint32_t& r2, uint32_t& r3,
                                        uint32_t addr) {
    asm volatile("ldmatrix.sync.aligned.m8n8.x4.shared.b16 {%0,%1,%2,%3}, [%4];"
                 : "=r"(r0), "=r"(r1), "=r"(r2), "=r"(r3) : "r"(addr));
}
__device__ __forceinline__ void mma16816(float& d0, float& d1, float& d2, float& d3,
                                         uint32_t a0, uint32_t a1, uint32_t a2, uint32_t a3,
                                         uint32_t b0, uint32_t b1) {
    asm volatile(
        "mma.sync.aligned.m16n8k16.row.col.f32.f16.f16.f32 "
        "{%0,%1,%2,%3}, {%4,%5,%6,%7}, {%8,%9}, {%0,%1,%2,%3};"
        : "+f"(d0), "+f"(d1), "+f"(d2), "+f"(d3)
        : "r"(a0), "r"(a1), "r"(a2), "r"(a3), "r"(b0), "r"(b1));
}

// ---------------------------------------------------------------------------
// Fused prep: per block (z, b-tile of 64):
//   E[192][64] in smem, then H rows (c for r<64, e shifted for r>=64),
//   written as fp16 straight to g_H [z][i'][b].
// ---------------------------------------------------------------------------
__global__ __launch_bounds__(256) void prep_kernel(const float* __restrict__ feat,
                                                   const float* __restrict__ geom,
                                                   const float* __restrict__ Wk) {
    extern __shared__ float sp[];
    float* s_wk = sp + PWK_F;
    float* s_E  = sp + PE_F;
    float4* s_gb = reinterpret_cast<float4*>(sp + PGB_F);

    const int z  = blockIdx.y;
    const int b0 = blockIdx.x * 64;
    const int t  = threadIdx.x;

    for (int m = t; m < 3 * 64 * 64 / 4; m += 256)
        reinterpret_cast<float4*>(s_wk)[m] = reinterpret_cast<const float4*>(Wk)[m];
    if (t < 64) {
        const float* gp = geom + ((size_t)z * NPTS + b0 + t) * 3;
        s_gb[t] = make_float4(gp[0], gp[1], gp[2], 0.0f);
    }

    const int bl = t & 63, q = t >> 6;
    float4 fr[16];
    const float4* fp = reinterpret_cast<const float4*>(
        feat + ((size_t)z * NPTS + b0 + bl) * CIN);
#pragma unroll
    for (int c = 0; c < 16; c++) fr[c] = fp[c];
    __syncthreads();

#pragma unroll 1
    for (int n = 0; n < 48; n++) {
        const int ii = q * 48 + n;
        const float4* w = reinterpret_cast<const float4*>(s_wk + ii * 64);
        float a0 = 0.f, a1 = 0.f, a2 = 0.f, a3 = 0.f;
#pragma unroll
        for (int c = 0; c < 16; c++) {
            const float4 wv = w[c];
            a0 = fmaf(fr[c].x, wv.x, a0);
            a1 = fmaf(fr[c].y, wv.y, a1);
            a2 = fmaf(fr[c].z, wv.z, a2);
            a3 = fmaf(fr[c].w, wv.w, a3);
        }
        s_E[ii * 72 + bl] = (a0 + a1) + (a2 + a3);
    }
    __syncthreads();

    // phase 2: warp w -> rows w*32..; lane l -> b pair (2l, 2l+1)
    const int wrp = t >> 5, l = t & 31;
    const float4 gbA = s_gb[2 * l];
    const float4 gbB = s_gb[2 * l + 1];
    uint32_t* Hh = reinterpret_cast<uint32_t*>(g_H);

#pragma unroll 1
    for (int rr = 0; rr < 32; rr++) {
        const int r = wrp * 32 + rr;
        float v0, v1;
        if (r < 64) {
            const float2 e0 = *reinterpret_cast<const float2*>(&s_E[r * 72 + 2 * l]);
            const float2 e1 = *reinterpret_cast<const float2*>(&s_E[(64 + r) * 72 + 2 * l]);
            const float2 e2 = *reinterpret_cast<const float2*>(&s_E[(128 + r) * 72 + 2 * l]);
            v0 = fmaf(gbA.x, e0.x, fmaf(gbA.y, e1.x, gbA.z * e2.x));
            v1 = fmaf(gbB.x, e0.y, fmaf(gbB.y, e1.y, gbB.z * e2.y));
        } else {
            const float2 e = *reinterpret_cast<const float2*>(&s_E[(r - 64) * 72 + 2 * l]);
            v0 = e.x; v1 = e.y;
        }
        const __half h0 = __float2half_rn(v0);
        const __half h1 = __float2half_rn(v1);
        const size_t idx = (((size_t)z * NIP + r) * NPTS + b0) / 2 + l;
        Hh[idx] = (uint32_t)__half_as_ushort(h0) | ((uint32_t)__half_as_ushort(h1) << 16);
    }
}

// issue one chunk's B copies (256 rows x 128B, SW128-swizzled)
__device__ __forceinline__ void issue_b_copies(uint32_t bst, int z, int b0, int t) {
#pragma unroll
    for (int it = 0; it < 8; it++) {
        const int m = t + THREADS * it;          // 0..2047
        const int row = m >> 3, c16 = m & 7;
        const uint32_t dst = bst + (uint32_t)row * 128u
                           + (uint32_t)((c16 ^ (row & 7)) << 4);
        const __half* src = g_H + (((size_t)z * NIP + row) * NPTS + b0 + c16 * 8);
        cpasync16(dst, src);
    }
}

// ---------------------------------------------------------------------------
// Main: per CTA (z, 64 a-rows): P[64 x 256] = M @ H (fp16 HMMA, fp32 accum).
// 8 warps, warp tile 32x64, one syncthreads per chunk, double-buffered B,
// mask tile A generated in-CTA from whole-z smem geometry.
// ---------------------------------------------------------------------------
__global__ __launch_bounds__(THREADS, 2) void conv_mma_kernel(
    const float* __restrict__ geom, float* __restrict__ out)
{
    extern __shared__ __align__(16) char smem[];
    const uint32_t su = smem_u32(smem);
    float4* g4 = reinterpret_cast<float4*>(smem);

    const int z  = blockIdx.y;
    const int a0 = blockIdx.x * MT;
    const int t  = threadIdx.x;
    const int wid = t >> 5, lane = t & 31;
    const int m0 = (wid >> 2) * 32, n0 = (wid & 3) * 64;

    const float* gz = geom + (size_t)z * NPTS * 3;

    // prologue: chunk-0 B copies + stage whole-z geometry as float4
    issue_b_copies(su + B_OFF, z, 0, t);
    asm volatile("cp.async.commit_group;" ::: "memory");
    {
        float* gf = reinterpret_cast<float*>(smem);
        for (int idx = t; idx < NPTS * 3; idx += THREADS)
            gf[(idx / 3) * 4 + (idx % 3)] = gz[idx];
    }
    __syncthreads();

    // maskgen consts: thread t -> row rg (0..63), k-quarter sg
    const int rg = t >> 2, sg = t & 3;
    const float4 ga = g4[a0 + rg];
    const uint32_t aw_base = su + A_OFF + (uint32_t)rg * 128u;
    const uint32_t rx = (uint32_t)(rg & 7);

    // ldsm lane bases
    const int rowA = m0 + ((lane >> 3) & 1) * 8 + (lane & 7);
    const uint32_t sA = (uint32_t)(lane >> 4), rxA = (uint32_t)(rowA & 7);
    const int rowB = n0 + ((lane >> 4) & 1) * 8 + (lane & 7);
    const uint32_t sB = (uint32_t)((lane >> 3) & 1), rxB = (uint32_t)(rowB & 7);

    float d[2][8][4];
#pragma unroll
    for (int mt = 0; mt < 2; mt++)
#pragma unroll
        for (int nt = 0; nt < 8; nt++)
#pragma unroll
            for (int r = 0; r < 4; r++) d[mt][nt][r] = 0.0f;

#pragma unroll 1
    for (int i = 0; i < NCHUNK; i++) {
        const uint32_t p = (uint32_t)(i & 1);
        const int b0 = i * KC;

        asm volatile("cp.async.wait_group 0;" ::: "memory");

        // ---- mask tile A[64 x 64] fp16 (SW128), diff-form norm test ----
        {
            const uint32_t ast = aw_base + p * A_STG;
#pragma unroll
            for (int v = 0; v < 8; v++) {
                const int veff = (v + sg) & 7;
                const int k0 = sg * 16 + 2 * veff;
                const float4 q0 = g4[b0 + k0];
                const float4 q1 = g4[b0 + k0 + 1];
                const float dx0 = q0.x - ga.x, dy0 = q0.y - ga.y, dz0 = q0.z - ga.z;
                const float dx1 = q1.x - ga.x, dy1 = q1.y - ga.y, dz1 = q1.z - ga.z;
                const float nn0 = fmaf(dx0, dx0, fmaf(dy0, dy0, dz0 * dz0));
                const float nn1 = fmaf(dx1, dx1, fmaf(dy1, dy1, dz1 * dz1));
                const uint32_t val = (nn0 < 1.0f ? 0x3C00u : 0u)
                                   | (nn1 < 1.0f ? 0x3C000000u : 0u);
                const uint32_t bc = (uint32_t)(2 * k0);
                sts32(ast + (((bc >> 4) ^ rx) << 4) + (bc & 15u), val);
            }
        }
        __syncthreads();   // A(p)+B(p) visible; all warps done with stage p^1

        if (i + 1 < NCHUNK) {
            issue_b_copies(su + B_OFF + (p ^ 1u) * B_STG, z, b0 + KC, t);
            asm volatile("cp.async.commit_group;" ::: "memory");
        }

        // ---- ldmatrix + 64 HMMA per warp ----
        {
            const uint32_t Ast = su + A_OFF + p * A_STG;
            const uint32_t Bst = su + B_OFF + p * B_STG;
#pragma unroll
            for (int kk = 0; kk < 4; kk++) {
                uint32_t af[2][4];
#pragma unroll
                for (int mt = 0; mt < 2; mt++)
                    ldsm_x4(af[mt][0], af[mt][1], af[mt][2], af[mt][3],
                            Ast + (uint32_t)(rowA + mt * 16) * 128u
                                + ((((uint32_t)kk * 2u + sA) ^ rxA) << 4));
#pragma unroll
                for (int ntp = 0; ntp < 4; ntp++) {
                    uint32_t b0r, b1r, b2r, b3r;
                    ldsm_x4(b0r, b1r, b2r, b3r,
                            Bst + (uint32_t)(rowB + ntp * 16) * 128u
                               + ((((uint32_t)kk * 2u + sB) ^ rxB) << 4));
#pragma unroll
                    for (int mt = 0; mt < 2; mt++) {
                        mma16816(d[mt][2*ntp][0], d[mt][2*ntp][1], d[mt][2*ntp][2], d[mt][2*ntp][3],
                                 af[mt][0], af[mt][1], af[mt][2], af[mt][3], b0r, b1r);
                        mma16816(d[mt][2*ntp+1][0], d[mt][2*ntp+1][1], d[mt][2*ntp+1][2], d[mt][2*ntp+1][3],
                                 af[mt][0], af[mt][1], af[mt][2], af[mt][3], b2r, b3r);
                    }
                }
            }
        }
    }

    // ---- epilogue: P (overlays A/B region), combine, store ----
    __syncthreads();
    float* P = reinterpret_cast<float*>(smem + A_OFF);   // [64][260]
    const int fr = lane >> 2, fc = lane & 3;
#pragma unroll
    for (int mt = 0; mt < 2; mt++) {
#pragma unroll
        for (int nt = 0; nt < 8; nt++) {
            const int R0 = m0 + mt * 16 + fr;
            const int C  = n0 + nt * 8 + 2 * fc;
            *reinterpret_cast<float2*>(P + R0 * 260 + C)       = make_float2(d[mt][nt][0], d[mt][nt][1]);
            *reinterpret_cast<float2*>(P + (R0 + 8) * 260 + C) = make_float2(d[mt][nt][2], d[mt][nt][3]);
        }
    }
    __syncthreads();

    {
        const int al = t >> 2, iq = t & 3;
        const float4 ga4 = g4[a0 + al];
        float* orow = out + ((size_t)z * NPTS + a0 + al) * 64;
        const float* Pr = P + al * 260;
#pragma unroll
        for (int u = 0; u < 4; u++) {
            const int i0 = iq * 16 + u * 4;
            const float4 vc = *reinterpret_cast<const float4*>(Pr + i0);
            const float4 v1 = *reinterpret_cast<const float4*>(Pr + 64 + i0);
            const float4 v2 = *reinterpret_cast<const float4*>(Pr + 128 + i0);
            const float4 v3 = *reinterpret_cast<const float4*>(Pr + 192 + i0);
            float4 o;
            o.x = fmaf(-ga4.z, v3.x, fmaf(-ga4.y, v2.x, fmaf(-ga4.x, v1.x, vc.x)));
            o.y = fmaf(-ga4.z, v3.y, fmaf(-ga4.y, v2.y, fmaf(-ga4.x, v1.y, vc.y)));
            o.z = fmaf(-ga4.z, v3.z, fmaf(-ga4.y, v2.z, fmaf(-ga4.x, v1.z, vc.z)));
            o.w = fmaf(-ga4.z, v3.w, fmaf(-ga4.y, v2.w, fmaf(-ga4.x, v1.w, vc.w)));
            *reinterpret_cast<float4*>(orow + i0) = o;
        }
    }
}

// ---------------------------------------------------------------------------
// Launcher. Inputs: features [8,2048,64] f32, geometry [8,2048,3] f32,
// Wk [3,64,64] f32. Output [8,2048,64] f32.
// ---------------------------------------------------------------------------
extern "C" void kernel_launch(void* const* d_in, const int* in_sizes, int n_in,
                              void* d_out, int out_size) {
    const float* feat = (const float*)d_in[0];
    const float* geom = (const float*)d_in[1];
    const float* Wk   = (const float*)d_in[2];
    float* out = (float*)d_out;
    (void)in_sizes; (void)n_in; (void)out_size;

    cudaFuncSetAttribute(prep_kernel,
                         cudaFuncAttributeMaxDynamicSharedMemorySize, SMEM_PREP);
    cudaFuncSetAttribute(conv_mma_kernel,
                         cudaFuncAttributeMaxDynamicSharedMemorySize, SMEM_MAIN);

    prep_kernel<<<dim3(NPTS / 64, BATCH), 256, SMEM_PREP>>>(feat, geom, Wk);
    conv_mma_kernel<<<dim3(NPTS / MT, BATCH), THREADS, SMEM_MAIN>>>(geom, out);
}